// round 14
// baseline (speedup 1.0000x reference)
#include <cuda_runtime.h>
#include <cuda_fp16.h>
#include <cstdint>

// Problem constants
#define BB 2
#define TT 2048
#define DD 1024
#define HH 16
#define DH 64
#define MM (BB*TT)          // 4096
#define N_QKV (3*DD)        // 3072

// ---------------------------------------------------------------------------
// Persistent fp16 scratch. Q keeps hi+lo (flash A operand); all else hi only.
// ---------------------------------------------------------------------------
__device__ __align__(16) __half Xh[MM*DD];            // hi only (A operand, 1-term)
__device__ __align__(16) __half Wah[DD*N_QKV];        // hi only (B operand)
__device__ __align__(16) __half Wph[DD*DD];           // hi only (B operand)
__device__ __align__(16) __half gQh[BB*HH*TT*DH], gQl[BB*HH*TT*DH];
__device__ __align__(16) __half gKh[BB*HH*TT*DH];     // hi only (B operand)
__device__ __align__(16) __half gVh[BB*HH*TT*DH];     // hi only (B operand)
__device__ __align__(16) __half gAh[MM*DD];           // hi only (A operand, 1-term)

// ---------------------------------------------------------------------------
// Helpers (baseline PTX: ldmatrix, mma.sync, cp.async — all sm_80)
// ---------------------------------------------------------------------------
__device__ __forceinline__ uint32_t smem_u32(const void* p) {
    uint32_t a;
    asm("{ .reg .u64 t; cvta.to.shared.u64 t, %1; cvt.u32.u64 %0, t; }"
        : "=r"(a) : "l"(p));
    return a;
}

__device__ __forceinline__ void ldm_x4(uint32_t* r, uint32_t addr) {
    asm volatile("ldmatrix.sync.aligned.m8n8.x4.shared.b16 {%0,%1,%2,%3}, [%4];"
                 : "=r"(r[0]), "=r"(r[1]), "=r"(r[2]), "=r"(r[3]) : "r"(addr));
}
__device__ __forceinline__ void ldm_x2(uint32_t* r, uint32_t addr) {
    asm volatile("ldmatrix.sync.aligned.m8n8.x2.shared.b16 {%0,%1}, [%2];"
                 : "=r"(r[0]), "=r"(r[1]) : "r"(addr));
}
__device__ __forceinline__ void ldm_x2t(uint32_t* r, uint32_t addr) {
    asm volatile("ldmatrix.sync.aligned.m8n8.x2.trans.shared.b16 {%0,%1}, [%2];"
                 : "=r"(r[0]), "=r"(r[1]) : "r"(addr));
}
__device__ __forceinline__ void mma_fp16(float* c, const uint32_t* a, const uint32_t* b) {
    asm volatile(
        "mma.sync.aligned.m16n8k16.row.col.f32.f16.f16.f32 "
        "{%0,%1,%2,%3}, {%4,%5,%6,%7}, {%8,%9}, {%0,%1,%2,%3};"
        : "+f"(c[0]), "+f"(c[1]), "+f"(c[2]), "+f"(c[3])
        : "r"(a[0]), "r"(a[1]), "r"(a[2]), "r"(a[3]), "r"(b[0]), "r"(b[1]));
}
__device__ __forceinline__ uint32_t pack_h2(__half a, __half b) {
    __half2 t(a, b);
    return *reinterpret_cast<uint32_t*>(&t);
}
__device__ __forceinline__ void split2h(float x, float y, uint32_t& hi, uint32_t& lo) {
    __half hx = __float2half(x);
    __half hy = __float2half(y);
    __half lx = __float2half(x - __half2float(hx));
    __half ly = __float2half(y - __half2float(hy));
    hi = pack_h2(hx, hy);
    lo = pack_h2(lx, ly);
}
__device__ __forceinline__ uint32_t h2_only(float x, float y) {
    return pack_h2(__float2half(x), __float2half(y));
}
__device__ __forceinline__ void cp16(uint32_t dst, const void* src) {
    asm volatile("cp.async.cg.shared.global [%0], [%1], 16;"
                 :: "r"(dst), "l"(src) : "memory");
}
#define CP_COMMIT() asm volatile("cp.async.commit_group;" ::: "memory")
#define CP_WAIT1()  asm volatile("cp.async.wait_group 1;" ::: "memory")
#define CP_WAIT0()  asm volatile("cp.async.wait_group 0;" ::: "memory")

// ---------------------------------------------------------------------------
// Prep kernels: f32 -> fp16 hi (all operands 1-term except Q, split later)
// ---------------------------------------------------------------------------
template <int WHICH>   // 0 = x, 1 = W_attn, 2 = W_proj
__global__ void prep_h(const float4* __restrict__ in, int n4)
{
    __half* oh = (WHICH == 0) ? Xh : ((WHICH == 1) ? Wah : Wph);
    const int i = blockIdx.x * blockDim.x + threadIdx.x;
    if (i < n4) {
        float4 v = __ldg(in + i);
        ((uint2*)oh)[i] = make_uint2(h2_only(v.x, v.y), h2_only(v.z, v.w));
    }
}

// ---------------------------------------------------------------------------
// Pipelined fp16 1-term tensor-core GEMM. Tile 128x128, BK=64.
// 512 thr / 16 warps (4x4), 32x32 warp tiles, 3-stage cp.async
// (3 x 32KB = 96KB smem), one __syncthreads per K-step, 1 MMA per k16.
// Stage layout: Ah@0 (16K) | Bh@16384 (16K).
// MODE 0: qkv (X x W_attn -> Q split / K hi / V hi). MODE 1: proj -> f32 C.
// ---------------------------------------------------------------------------
#define BM 128
#define BN 128
#define GSTG 32768
#define GSMEM (3 * GSTG)

template <int MODE>
__global__ __launch_bounds__(512, 1) void gemm2(
    const float* __restrict__ bias, float* __restrict__ C)
{
    extern __shared__ char smem[];
    const uint32_t sbase = smem_u32(smem);
    const __half* Ahp = (MODE == 0) ? Xh : gAh;
    const __half* Bhp = (MODE == 0) ? Wah : Wph;
    const int Nn = (MODE == 0) ? N_QKV : DD;
    const int n0 = blockIdx.x * BN;
    const int m0 = blockIdx.y * BM;
    const int tid = threadIdx.x;
    const int lane = tid & 31;
    const int wid = tid >> 5;
    const int wm = wid & 3;       // rows wm*32
    const int wn = wid >> 2;      // cols wn*32

    auto issue = [&](int step) {
        const uint32_t sb = sbase + (step % 3) * GSTG;
        const int k0 = step * 64;
        {   // A tile: 128 rows x 64 fp16; 4 threads/row, 2 chunks each
            const int r = tid >> 2, c0 = (tid & 3) * 2;
            const __half* sh = Ahp + (size_t)(m0 + r) * DD + k0 + c0 * 8;
            const uint32_t db = sb + r * 128;
#pragma unroll
            for (int i = 0; i < 2; i++) {
                const int c = c0 + i;
                const uint32_t sw = (uint32_t)(((c ^ r) & 7) * 16);
                cp16(db + sw, sh + i * 8);
            }
        }
        {   // B tile: 64 rows x 128 fp16; 8 threads/row, 2 chunks each
            const int r = tid >> 3, c0 = (tid & 7) * 2;
            const __half* sh = Bhp + (size_t)(k0 + r) * Nn + n0 + c0 * 8;
            const uint32_t db = sb + 16384 + r * 256;
#pragma unroll
            for (int i = 0; i < 2; i++) {
                const int c = c0 + i;
                const uint32_t sw = (uint32_t)((((c & 8) | ((c ^ r) & 7))) * 16);
                cp16(db + sw, sh + i * 8);
            }
        }
    };

    float acc[2][4][4];
#pragma unroll
    for (int mt = 0; mt < 2; mt++)
#pragma unroll
        for (int nt = 0; nt < 4; nt++)
#pragma unroll
            for (int e = 0; e < 4; e++) acc[mt][nt][e] = 0.f;

    issue(0); CP_COMMIT();
    issue(1); CP_COMMIT();

    for (int step = 0; step < 16; step++) {
        if (step == 15) { CP_WAIT0(); } else { CP_WAIT1(); }
        __syncthreads();

        const uint32_t sb = sbase + (step % 3) * GSTG;
#pragma unroll
        for (int kk = 0; kk < 4; kk++) {
            uint32_t ah[2][4];
            const int rb = wm * 32 + (lane & 7) + ((lane >> 3) & 1) * 8;
            const int ch = kk * 2 + (lane >> 4);
#pragma unroll
            for (int mt = 0; mt < 2; mt++) {
                const int r = rb + mt * 16;
                const uint32_t off = (uint32_t)(r * 128 + ((ch ^ r) & 7) * 16);
                ldm_x4(ah[mt], sb + off);
            }
            uint32_t bh[4][2];
            const int kr = kk * 16 + (lane & 15);
#pragma unroll
            for (int nt = 0; nt < 4; nt++) {
                const int cB = wn * 4 + nt;
                const uint32_t off =
                    (uint32_t)(kr * 256 + ((cB & 8) | ((cB ^ kr) & 7)) * 16);
                ldm_x2t(bh[nt], sb + 16384 + off);
            }
#pragma unroll
            for (int mt = 0; mt < 2; mt++)
#pragma unroll
                for (int nt = 0; nt < 4; nt++)
                    mma_fp16(acc[mt][nt], ah[mt], bh[nt]);
        }

        if (step + 2 < 16) { issue(step + 2); CP_COMMIT(); }
    }

    // epilogue
#pragma unroll
    for (int mt = 0; mt < 2; mt++) {
        const int rb = m0 + wm * 32 + mt * 16 + (lane >> 2);
#pragma unroll
        for (int nt = 0; nt < 4; nt++) {
            const int col = n0 + wn * 32 + nt * 8 + (lane & 3) * 2;
            const float2 bv = *(const float2*)(bias + col);
#pragma unroll
            for (int rr = 0; rr < 2; rr++) {
                const int m = rb + rr * 8;
                float vx = acc[mt][nt][rr * 2 + 0] + bv.x;
                float vy = acc[mt][nt][rr * 2 + 1] + bv.y;
                if (MODE == 0) {
                    const int which = col >> 10;
                    const int h = (col & (DD - 1)) >> 6;
                    const int dd = col & (DH - 1);
                    const int b = m >> 11, t = m & (TT - 1);
                    const size_t idx = (((size_t)(b * HH + h) * TT) + t) * DH + dd;
                    if (which == 0) {          // Q: pre-scale + hi/lo split
                        uint32_t hi, lo;
                        split2h(vx * 0.125f, vy * 0.125f, hi, lo);
                        *(uint32_t*)(gQh + idx) = hi;
                        *(uint32_t*)(gQl + idx) = lo;
                    } else if (which == 1) {   // K: hi only
                        *(uint32_t*)(gKh + idx) = h2_only(vx, vy);
                    } else {                   // V: hi only
                        *(uint32_t*)(gVh + idx) = h2_only(vx, vy);
                    }
                } else {
                    *(float2*)(C + (size_t)m * DD + col) = make_float2(vx, vy);
                }
            }
        }
    }
}

// ---------------------------------------------------------------------------
// Tensor-core flash attention, fp16 (unchanged from R13). QK: 2-term Q split;
// PV: P hi only. Output gA hi only.
// smem: Qh 8K | Ql 8K | 2 stages x (Kh 8K | Vh 8K) = 48KB total.
// ---------------------------------------------------------------------------
#define FSTG 16384

__global__ __launch_bounds__(128) void flash2()
{
    extern __shared__ char smem[];
    const uint32_t sbase = smem_u32(smem);
    const int bh = blockIdx.x;
    const int qt = gridDim.y - 1 - blockIdx.y;      // big tiles first
    const int q0 = qt * 64;
    const int tid = threadIdx.x;
    const int lane = tid & 31;
    const int wq = tid >> 5;
    const size_t hoff = (size_t)bh * TT * DH;

    // ---- stage Q hi/lo
    {
        const int r = tid >> 1, cb = (tid & 1) * 4;
        const size_t go = hoff + (size_t)(q0 + r) * DH + cb * 8;
        const uint32_t db = sbase + r * 128;
#pragma unroll
        for (int i = 0; i < 4; i++) {
            const int c = cb + i;
            const uint32_t sw = (uint32_t)(((c ^ r) & 7) * 16);
            cp16(db + sw, gQh + go + i * 8);
            cp16(db + 8192 + sw, gQl + go + i * 8);
        }
    }
    CP_COMMIT();

    auto issueKV = [&](int jt) {
        const uint32_t db0 = sbase + 16384 + (jt & 1) * FSTG;
        const int j0 = jt * 64;
        const int r = tid >> 1, cb = (tid & 1) * 4;
        const size_t go = hoff + (size_t)(j0 + r) * DH + cb * 8;
        const uint32_t db = db0 + r * 128;
#pragma unroll
        for (int i = 0; i < 4; i++) {
            const int c = cb + i;
            const uint32_t sw = (uint32_t)(((c ^ r) & 7) * 16);
            cp16(db + sw,        gKh + go + i * 8);
            cp16(db + 8192 + sw, gVh + go + i * 8);
        }
    };

    issueKV(0); CP_COMMIT();
    CP_WAIT1(); __syncthreads();

    uint32_t qh[4][4], ql[4][4];
    {
        const int r = wq * 16 + (lane & 7) + ((lane >> 3) & 1) * 8;
#pragma unroll
        for (int ks = 0; ks < 4; ks++) {
            const int ch = ks * 2 + (lane >> 4);
            const uint32_t off = (uint32_t)(r * 128 + ((ch ^ r) & 7) * 16);
            ldm_x4(qh[ks], sbase + off);
            ldm_x4(ql[ks], sbase + 8192 + off);
        }
    }

    float o[8][4];
#pragma unroll
    for (int nt = 0; nt < 8; nt++)
#pragma unroll
        for (int e = 0; e < 4; e++) o[nt][e] = 0.f;
    float m0r = -1e30f, m1r = -1e30f, l0r = 0.f, l1r = 0.f;
    const int row0 = wq * 16 + (lane >> 2);

    for (int jt = 0; jt <= qt; jt++) {
        if (jt + 1 <= qt) { issueKV(jt + 1); CP_COMMIT(); CP_WAIT1(); }
        else              { CP_WAIT0(); }
        __syncthreads();

        const uint32_t kb = sbase + 16384 + (jt & 1) * FSTG;
        const uint32_t vb = kb + 8192;

        // ---- S = Q K^T (2 MMAs per tile: Qh*K + Ql*K)
        float sc[8][4];
#pragma unroll
        for (int nt = 0; nt < 8; nt++)
#pragma unroll
            for (int e = 0; e < 4; e++) sc[nt][e] = 0.f;

#pragma unroll
        for (int ks = 0; ks < 4; ks++) {
            uint32_t bh2[8][2];
            const int ln = lane & 15;
            const int ch = ks * 2 + ((ln >> 3) & 1);
#pragma unroll
            for (int nt = 0; nt < 8; nt++) {
                const int r = nt * 8 + (ln & 7);
                const uint32_t off = (uint32_t)(r * 128 + ((ch ^ r) & 7) * 16);
                ldm_x2(bh2[nt], kb + off);
            }
#pragma unroll
            for (int nt = 0; nt < 8; nt++) {
                mma_fp16(sc[nt], qh[ks], bh2[nt]);
                mma_fp16(sc[nt], ql[ks], bh2[nt]);
            }
        }

        // ---- causal mask on diagonal tile
        if (jt == qt) {
            const int cbase = (lane & 3) * 2;
#pragma unroll
            for (int nt = 0; nt < 8; nt++) {
                const int c0 = nt * 8 + cbase;
                if (c0 > row0)         sc[nt][0] = -1e30f;
                if (c0 + 1 > row0)     sc[nt][1] = -1e30f;
                if (c0 > row0 + 8)     sc[nt][2] = -1e30f;
                if (c0 + 1 > row0 + 8) sc[nt][3] = -1e30f;
            }
        }

        // ---- online softmax
        float mx0 = -1e30f, mx1 = -1e30f;
#pragma unroll
        for (int nt = 0; nt < 8; nt++) {
            mx0 = fmaxf(mx0, fmaxf(sc[nt][0], sc[nt][1]));
            mx1 = fmaxf(mx1, fmaxf(sc[nt][2], sc[nt][3]));
        }
        mx0 = fmaxf(mx0, __shfl_xor_sync(0xffffffffu, mx0, 1));
        mx0 = fmaxf(mx0, __shfl_xor_sync(0xffffffffu, mx0, 2));
        mx1 = fmaxf(mx1, __shfl_xor_sync(0xffffffffu, mx1, 1));
        mx1 = fmaxf(mx1, __shfl_xor_sync(0xffffffffu, mx1, 2));

        const float mn0 = fmaxf(m0r, mx0);
        const float mn1 = fmaxf(m1r, mx1);
        const float c0 = __expf(m0r - mn0);
        const float c1 = __expf(m1r - mn1);

        float sum0 = 0.f, sum1 = 0.f;
#pragma unroll
        for (int nt = 0; nt < 8; nt++) {
            sc[nt][0] = __expf(sc[nt][0] - mn0);
            sc[nt][1] = __expf(sc[nt][1] - mn0);
            sc[nt][2] = __expf(sc[nt][2] - mn1);
            sc[nt][3] = __expf(sc[nt][3] - mn1);
            sum0 += sc[nt][0] + sc[nt][1];
            sum1 += sc[nt][2] + sc[nt][3];
        }
        sum0 += __shfl_xor_sync(0xffffffffu, sum0, 1);
        sum0 += __shfl_xor_sync(0xffffffffu, sum0, 2);
        sum1 += __shfl_xor_sync(0xffffffffu, sum1, 1);
        sum1 += __shfl_xor_sync(0xffffffffu, sum1, 2);

        l0r = l0r * c0 + sum0;
        l1r = l1r * c1 + sum1;
        m0r = mn0;
        m1r = mn1;

#pragma unroll
        for (int nt = 0; nt < 8; nt++) {
            o[nt][0] *= c0; o[nt][1] *= c0;
            o[nt][2] *= c1; o[nt][3] *= c1;
        }

        // ---- P V (P hi only -> 1 MMA per tile)
#pragma unroll
        for (int ks = 0; ks < 4; ks++) {
            uint32_t ph[4];
            ph[0] = h2_only(sc[2 * ks][0],     sc[2 * ks][1]);
            ph[1] = h2_only(sc[2 * ks][2],     sc[2 * ks][3]);
            ph[2] = h2_only(sc[2 * ks + 1][0], sc[2 * ks + 1][1]);
            ph[3] = h2_only(sc[2 * ks + 1][2], sc[2 * ks + 1][3]);

            const int kr = ks * 16 + (lane & 15);
#pragma unroll
            for (int nt = 0; nt < 8; nt++) {
                uint32_t vh[2];
                const uint32_t off = (uint32_t)(kr * 128 + ((nt ^ kr) & 7) * 16);
                ldm_x2t(vh, vb + off);
                mma_fp16(o[nt], ph, vh);
            }
        }
        __syncthreads();
    }

    // ---- epilogue: write gA hi only
    const float inv0 = 1.f / l0r;
    const float inv1 = 1.f / l1r;
    const int b = bh >> 4, h = bh & 15;
    const int t0 = q0 + row0;
#pragma unroll
    for (int nt = 0; nt < 8; nt++) {
        const int col = h * DH + nt * 8 + (lane & 3) * 2;
        *(uint32_t*)(gAh + (size_t)(b * TT + t0) * DD + col) =
            h2_only(o[nt][0] * inv0, o[nt][1] * inv0);
        *(uint32_t*)(gAh + (size_t)(b * TT + t0 + 8) * DD + col) =
            h2_only(o[nt][2] * inv1, o[nt][3] * inv1);
    }
}

// ---------------------------------------------------------------------------
// Launcher
// ---------------------------------------------------------------------------
extern "C" void kernel_launch(void* const* d_in, const int* in_sizes, int n_in,
                              void* d_out, int out_size)
{
    const float* x      = (const float*)d_in[0];
    const float* W_attn = (const float*)d_in[1];
    const float* b_attn = (const float*)d_in[2];
    const float* W_proj = (const float*)d_in[3];
    const float* b_proj = (const float*)d_in[4];
    float* out = (float*)d_out;

    cudaFuncSetAttribute(gemm2<0>, cudaFuncAttributeMaxDynamicSharedMemorySize, GSMEM);
    cudaFuncSetAttribute(gemm2<1>, cudaFuncAttributeMaxDynamicSharedMemorySize, GSMEM);
    cudaFuncSetAttribute(flash2,   cudaFuncAttributeMaxDynamicSharedMemorySize, 49152);

    prep_h<0><<<(MM * DD / 4 + 255) / 256, 256>>>((const float4*)x, MM * DD / 4);
    prep_h<1><<<(DD * N_QKV / 4 + 255) / 256, 256>>>((const float4*)W_attn, DD * N_QKV / 4);
    prep_h<2><<<(DD * DD / 4 + 255) / 256, 256>>>((const float4*)W_proj, DD * DD / 4);

    dim3 g1(N_QKV / BN, MM / BM);       // 24 x 32
    gemm2<0><<<g1, 512, GSMEM>>>(b_attn, nullptr);

    dim3 g2(BB * HH, TT / 64);          // 32 x 32
    flash2<<<g2, 128, 49152>>>();

    dim3 g3(DD / BN, MM / BM);          // 8 x 32
    gemm2<1><<<g3, 512, GSMEM>>>(b_proj, out);
}

// round 15
// speedup vs baseline: 1.2932x; 1.2932x over previous
#include <cuda_runtime.h>
#include <cuda_fp16.h>
#include <cstdint>

// Problem constants
#define BB 2
#define TT 2048
#define DD 1024
#define HH 16
#define DH 64
#define MM (BB*TT)          // 4096
#define N_QKV (3*DD)        // 3072

// ---------------------------------------------------------------------------
// Persistent split-fp16 scratch. X and Q keep hi+lo; everything else hi only.
// ---------------------------------------------------------------------------
__device__ __align__(16) __half Xh[MM*DD],  Xl[MM*DD];
__device__ __align__(16) __half Wah[DD*N_QKV];        // hi only (B operand)
__device__ __align__(16) __half Wph[DD*DD];           // hi only (B operand)
__device__ __align__(16) __half gQh[BB*HH*TT*DH], gQl[BB*HH*TT*DH];
__device__ __align__(16) __half gKh[BB*HH*TT*DH];     // hi only (B operand)
__device__ __align__(16) __half gVh[BB*HH*TT*DH];     // hi only (B operand)
__device__ __align__(16) __half gAh[MM*DD];           // hi only (A operand, 1-term proj)

// ---------------------------------------------------------------------------
// Helpers (baseline PTX: ldmatrix, mma.sync, cp.async — all sm_80)
// ---------------------------------------------------------------------------
__device__ __forceinline__ uint32_t smem_u32(const void* p) {
    uint32_t a;
    asm("{ .reg .u64 t; cvta.to.shared.u64 t, %1; cvt.u32.u64 %0, t; }"
        : "=r"(a) : "l"(p));
    return a;
}

__device__ __forceinline__ void ldm_x4(uint32_t* r, uint32_t addr) {
    asm volatile("ldmatrix.sync.aligned.m8n8.x4.shared.b16 {%0,%1,%2,%3}, [%4];"
                 : "=r"(r[0]), "=r"(r[1]), "=r"(r[2]), "=r"(r[3]) : "r"(addr));
}
__device__ __forceinline__ void ldm_x2(uint32_t* r, uint32_t addr) {
    asm volatile("ldmatrix.sync.aligned.m8n8.x2.shared.b16 {%0,%1}, [%2];"
                 : "=r"(r[0]), "=r"(r[1]) : "r"(addr));
}
__device__ __forceinline__ void ldm_x2t(uint32_t* r, uint32_t addr) {
    asm volatile("ldmatrix.sync.aligned.m8n8.x2.trans.shared.b16 {%0,%1}, [%2];"
                 : "=r"(r[0]), "=r"(r[1]) : "r"(addr));
}
__device__ __forceinline__ void mma_fp16(float* c, const uint32_t* a, const uint32_t* b) {
    asm volatile(
        "mma.sync.aligned.m16n8k16.row.col.f32.f16.f16.f32 "
        "{%0,%1,%2,%3}, {%4,%5,%6,%7}, {%8,%9}, {%0,%1,%2,%3};"
        : "+f"(c[0]), "+f"(c[1]), "+f"(c[2]), "+f"(c[3])
        : "r"(a[0]), "r"(a[1]), "r"(a[2]), "r"(a[3]), "r"(b[0]), "r"(b[1]));
}
__device__ __forceinline__ uint32_t pack_h2(__half a, __half b) {
    __half2 t(a, b);
    return *reinterpret_cast<uint32_t*>(&t);
}
__device__ __forceinline__ void split2h(float x, float y, uint32_t& hi, uint32_t& lo) {
    __half hx = __float2half(x);
    __half hy = __float2half(y);
    __half lx = __float2half(x - __half2float(hx));
    __half ly = __float2half(y - __half2float(hy));
    hi = pack_h2(hx, hy);
    lo = pack_h2(lx, ly);
}
__device__ __forceinline__ uint32_t h2_only(float x, float y) {
    return pack_h2(__float2half(x), __float2half(y));
}
__device__ __forceinline__ void cp16(uint32_t dst, const void* src) {
    asm volatile("cp.async.cg.shared.global [%0], [%1], 16;"
                 :: "r"(dst), "l"(src) : "memory");
}
#define CP_COMMIT() asm volatile("cp.async.commit_group;" ::: "memory")
#define CP_WAIT1()  asm volatile("cp.async.wait_group 1;" ::: "memory")
#define CP_WAIT0()  asm volatile("cp.async.wait_group 0;" ::: "memory")

// ---------------------------------------------------------------------------
// Prep kernels (R13 form: X split hi/lo, weights hi only)
// ---------------------------------------------------------------------------
__global__ void prep_x(const float4* __restrict__ in, int n4)
{
    const int i = blockIdx.x * blockDim.x + threadIdx.x;
    if (i < n4) {
        float4 v = __ldg(in + i);
        uint32_t h0, l0, h1, l1;
        split2h(v.x, v.y, h0, l0);
        split2h(v.z, v.w, h1, l1);
        ((uint2*)Xh)[i] = make_uint2(h0, h1);
        ((uint2*)Xl)[i] = make_uint2(l0, l1);
    }
}
template <int WHICH>   // 1 = W_attn, 2 = W_proj
__global__ void prep_w(const float4* __restrict__ in, int n4)
{
    __half* oh = (WHICH == 1) ? Wah : Wph;
    const int i = blockIdx.x * blockDim.x + threadIdx.x;
    if (i < n4) {
        float4 v = __ldg(in + i);
        ((uint2*)oh)[i] = make_uint2(h2_only(v.x, v.y), h2_only(v.z, v.w));
    }
}

// ---------------------------------------------------------------------------
// Pipelined fp16 tensor-core GEMM (exact R13: 512 thr / 16 warps, 32x32 warp
// tiles, 3-stage cp.async, one __syncthreads per K-step).
// MODE 0 (qkv): A = X hi+lo (2 MMAs/k16). MODE 1 (proj): A = gA hi (1 MMA).
// Stage layout: Ah@0 (16K) | Al@16384 (16K, MODE0 only) | Bh@32768 (16K).
// ---------------------------------------------------------------------------
#define BM 128
#define BN 128
#define GSTG 49152
#define GSMEM (3 * GSTG)

template <int MODE>
__global__ __launch_bounds__(512, 1) void gemm2(
    const float* __restrict__ bias, float* __restrict__ C)
{
    extern __shared__ char smem[];
    const uint32_t sbase = smem_u32(smem);
    const __half* Ahp = (MODE == 0) ? Xh : gAh;
    const __half* Alp = Xl;                      // only used when MODE == 0
    const __half* Bhp = (MODE == 0) ? Wah : Wph;
    const int Nn = (MODE == 0) ? N_QKV : DD;
    const int n0 = blockIdx.x * BN;
    const int m0 = blockIdx.y * BM;
    const int tid = threadIdx.x;
    const int lane = tid & 31;
    const int wid = tid >> 5;
    const int wm = wid & 3;       // rows wm*32
    const int wn = wid >> 2;      // cols wn*32

    auto issue = [&](int step) {
        const uint32_t sb = sbase + (step % 3) * GSTG;
        const int k0 = step * 64;
        {   // A tile: 128 rows x 64 fp16; 4 threads/row, 2 chunks each
            const int r = tid >> 2, c0 = (tid & 3) * 2;
            const __half* sh = Ahp + (size_t)(m0 + r) * DD + k0 + c0 * 8;
            const __half* sl = Alp + (size_t)(m0 + r) * DD + k0 + c0 * 8;
            const uint32_t db = sb + r * 128;
#pragma unroll
            for (int i = 0; i < 2; i++) {
                const int c = c0 + i;
                const uint32_t sw = (uint32_t)(((c ^ r) & 7) * 16);
                cp16(db + sw, sh + i * 8);
                if (MODE == 0) cp16(db + 16384 + sw, sl + i * 8);
            }
        }
        {   // B tile (hi only): 64 rows x 128 fp16; 8 threads/row, 2 chunks each
            const int r = tid >> 3, c0 = (tid & 7) * 2;
            const __half* sh = Bhp + (size_t)(k0 + r) * Nn + n0 + c0 * 8;
            const uint32_t db = sb + 32768 + r * 256;
#pragma unroll
            for (int i = 0; i < 2; i++) {
                const int c = c0 + i;
                const uint32_t sw = (uint32_t)((((c & 8) | ((c ^ r) & 7))) * 16);
                cp16(db + sw, sh + i * 8);
            }
        }
    };

    float acc[2][4][4];
#pragma unroll
    for (int mt = 0; mt < 2; mt++)
#pragma unroll
        for (int nt = 0; nt < 4; nt++)
#pragma unroll
            for (int e = 0; e < 4; e++) acc[mt][nt][e] = 0.f;

    issue(0); CP_COMMIT();
    issue(1); CP_COMMIT();

    for (int step = 0; step < 16; step++) {
        if (step == 15) { CP_WAIT0(); } else { CP_WAIT1(); }
        __syncthreads();

        const uint32_t sb = sbase + (step % 3) * GSTG;
#pragma unroll
        for (int kk = 0; kk < 4; kk++) {
            uint32_t ah[2][4], al[2][4];
            const int rb = wm * 32 + (lane & 7) + ((lane >> 3) & 1) * 8;
            const int ch = kk * 2 + (lane >> 4);
#pragma unroll
            for (int mt = 0; mt < 2; mt++) {
                const int r = rb + mt * 16;
                const uint32_t off = (uint32_t)(r * 128 + ((ch ^ r) & 7) * 16);
                ldm_x4(ah[mt], sb + off);
                if (MODE == 0) ldm_x4(al[mt], sb + 16384 + off);
            }
            uint32_t bh[4][2];
            const int kr = kk * 16 + (lane & 15);
#pragma unroll
            for (int nt = 0; nt < 4; nt++) {
                const int cB = wn * 4 + nt;
                const uint32_t off =
                    (uint32_t)(kr * 256 + ((cB & 8) | ((cB ^ kr) & 7)) * 16);
                ldm_x2t(bh[nt], sb + 32768 + off);
            }
#pragma unroll
            for (int mt = 0; mt < 2; mt++)
#pragma unroll
                for (int nt = 0; nt < 4; nt++) {
                    mma_fp16(acc[mt][nt], ah[mt], bh[nt]);
                    if (MODE == 0) mma_fp16(acc[mt][nt], al[mt], bh[nt]);
                }
        }

        if (step + 2 < 16) { issue(step + 2); CP_COMMIT(); }
    }

    // epilogue
#pragma unroll
    for (int mt = 0; mt < 2; mt++) {
        const int rb = m0 + wm * 32 + mt * 16 + (lane >> 2);
#pragma unroll
        for (int nt = 0; nt < 4; nt++) {
            const int col = n0 + wn * 32 + nt * 8 + (lane & 3) * 2;
            const float2 bv = *(const float2*)(bias + col);
#pragma unroll
            for (int rr = 0; rr < 2; rr++) {
                const int m = rb + rr * 8;
                float vx = acc[mt][nt][rr * 2 + 0] + bv.x;
                float vy = acc[mt][nt][rr * 2 + 1] + bv.y;
                if (MODE == 0) {
                    const int which = col >> 10;
                    const int h = (col & (DD - 1)) >> 6;
                    const int dd = col & (DH - 1);
                    const int b = m >> 11, t = m & (TT - 1);
                    const size_t idx = (((size_t)(b * HH + h) * TT) + t) * DH + dd;
                    if (which == 0) {          // Q: pre-scale + hi/lo split
                        uint32_t hi, lo;
                        split2h(vx * 0.125f, vy * 0.125f, hi, lo);
                        *(uint32_t*)(gQh + idx) = hi;
                        *(uint32_t*)(gQl + idx) = lo;
                    } else if (which == 1) {   // K: hi only
                        *(uint32_t*)(gKh + idx) = h2_only(vx, vy);
                    } else {                   // V: hi only
                        *(uint32_t*)(gVh + idx) = h2_only(vx, vy);
                    }
                } else {
                    *(float2*)(C + (size_t)m * DD + col) = make_float2(vx, vy);
                }
            }
        }
    }
}

// ---------------------------------------------------------------------------
// Tensor-core flash attention, fp16. 128-row q-tiles, 256 thr / 8 warps
// (16 rows per warp, same inner structure as R13). QK: 2-term Q split;
// PV: P hi only. Output gA hi only.
// smem: Qh 16K | Ql 16K | 2 stages x (Kh 8K | Vh 8K) = 64KB.
// K/V global traffic halves vs 64-row tiles; CTA count halves.
// ---------------------------------------------------------------------------
#define FSTG 16384

__global__ __launch_bounds__(256) void flash2()
{
    extern __shared__ char smem[];
    const uint32_t sbase = smem_u32(smem);
    const int bh = blockIdx.x;
    const int qt = gridDim.y - 1 - blockIdx.y;      // big tiles first
    const int q0 = qt * 128;
    const int tid = threadIdx.x;
    const int lane = tid & 31;
    const int wq = tid >> 5;                        // 0..7 -> rows wq*16
    const size_t hoff = (size_t)bh * TT * DH;

    // ---- stage Q hi/lo (128 rows)
    {
        const int r = tid >> 1, cb = (tid & 1) * 4;
        const size_t go = hoff + (size_t)(q0 + r) * DH + cb * 8;
        const uint32_t db = sbase + r * 128;
#pragma unroll
        for (int i = 0; i < 4; i++) {
            const int c = cb + i;
            const uint32_t sw = (uint32_t)(((c ^ r) & 7) * 16);
            cp16(db + sw, gQh + go + i * 8);
            cp16(db + 16384 + sw, gQl + go + i * 8);
        }
    }
    CP_COMMIT();

    const int njt = 2 * qt + 2;   // j-tiles (64 keys each) covering q0+127

    auto issueKV = [&](int jt) {
        const uint32_t db0 = sbase + 32768 + (jt & 1) * FSTG;
        const int j0 = jt * 64;
        const int r = tid >> 2, c0 = (tid & 3) * 2;
        const size_t go = hoff + (size_t)(j0 + r) * DH + c0 * 8;
        const uint32_t db = db0 + r * 128;
#pragma unroll
        for (int i = 0; i < 2; i++) {
            const int c = c0 + i;
            const uint32_t sw = (uint32_t)(((c ^ r) & 7) * 16);
            cp16(db + sw,        gKh + go + i * 8);
            cp16(db + 8192 + sw, gVh + go + i * 8);
        }
    };

    issueKV(0); CP_COMMIT();
    CP_WAIT1(); __syncthreads();

    uint32_t qh[4][4], ql[4][4];
    {
        const int r = wq * 16 + (lane & 7) + ((lane >> 3) & 1) * 8;
#pragma unroll
        for (int ks = 0; ks < 4; ks++) {
            const int ch = ks * 2 + (lane >> 4);
            const uint32_t off = (uint32_t)(r * 128 + ((ch ^ r) & 7) * 16);
            ldm_x4(qh[ks], sbase + off);
            ldm_x4(ql[ks], sbase + 16384 + off);
        }
    }

    float o[8][4];
#pragma unroll
    for (int nt = 0; nt < 8; nt++)
#pragma unroll
        for (int e = 0; e < 4; e++) o[nt][e] = 0.f;
    float m0r = -1e30f, m1r = -1e30f, l0r = 0.f, l1r = 0.f;
    const int row0 = wq * 16 + (lane >> 2);   // local q row (also +8)

    for (int jt = 0; jt < njt; jt++) {
        if (jt + 1 < njt) { issueKV(jt + 1); CP_COMMIT(); CP_WAIT1(); }
        else              { CP_WAIT0(); }
        __syncthreads();

        const uint32_t kb = sbase + 32768 + (jt & 1) * FSTG;
        const uint32_t vb = kb + 8192;

        // ---- S = Q K^T (2 MMAs per tile: Qh*K + Ql*K)
        float sc[8][4];
#pragma unroll
        for (int nt = 0; nt < 8; nt++)
#pragma unroll
            for (int e = 0; e < 4; e++) sc[nt][e] = 0.f;

#pragma unroll
        for (int ks = 0; ks < 4; ks++) {
            uint32_t bh2[8][2];
            const int ln = lane & 15;
            const int ch = ks * 2 + ((ln >> 3) & 1);
#pragma unroll
            for (int nt = 0; nt < 8; nt++) {
                const int r = nt * 8 + (ln & 7);
                const uint32_t off = (uint32_t)(r * 128 + ((ch ^ r) & 7) * 16);
                ldm_x2(bh2[nt], kb + off);
            }
#pragma unroll
            for (int nt = 0; nt < 8; nt++) {
                mma_fp16(sc[nt], qh[ks], bh2[nt]);
                mma_fp16(sc[nt], ql[ks], bh2[nt]);
            }
        }

        // ---- causal mask (last two j-tiles intersect the diagonal)
        if (jt >= 2 * qt) {
            const int j0 = jt * 64;
            const int cbase = j0 + (lane & 3) * 2;
            const int rg0 = q0 + row0;
#pragma unroll
            for (int nt = 0; nt < 8; nt++) {
                const int c0 = cbase + nt * 8;
                if (c0 > rg0)         sc[nt][0] = -1e30f;
                if (c0 + 1 > rg0)     sc[nt][1] = -1e30f;
                if (c0 > rg0 + 8)     sc[nt][2] = -1e30f;
                if (c0 + 1 > rg0 + 8) sc[nt][3] = -1e30f;
            }
        }

        // ---- online softmax
        float mx0 = -1e30f, mx1 = -1e30f;
#pragma unroll
        for (int nt = 0; nt < 8; nt++) {
            mx0 = fmaxf(mx0, fmaxf(sc[nt][0], sc[nt][1]));
            mx1 = fmaxf(mx1, fmaxf(sc[nt][2], sc[nt][3]));
        }
        mx0 = fmaxf(mx0, __shfl_xor_sync(0xffffffffu, mx0, 1));
        mx0 = fmaxf(mx0, __shfl_xor_sync(0xffffffffu, mx0, 2));
        mx1 = fmaxf(mx1, __shfl_xor_sync(0xffffffffu, mx1, 1));
        mx1 = fmaxf(mx1, __shfl_xor_sync(0xffffffffu, mx1, 2));

        const float mn0 = fmaxf(m0r, mx0);
        const float mn1 = fmaxf(m1r, mx1);
        const float c0 = __expf(m0r - mn0);
        const float c1 = __expf(m1r - mn1);

        float sum0 = 0.f, sum1 = 0.f;
#pragma unroll
        for (int nt = 0; nt < 8; nt++) {
            sc[nt][0] = __expf(sc[nt][0] - mn0);
            sc[nt][1] = __expf(sc[nt][1] - mn0);
            sc[nt][2] = __expf(sc[nt][2] - mn1);
            sc[nt][3] = __expf(sc[nt][3] - mn1);
            sum0 += sc[nt][0] + sc[nt][1];
            sum1 += sc[nt][2] + sc[nt][3];
        }
        sum0 += __shfl_xor_sync(0xffffffffu, sum0, 1);
        sum0 += __shfl_xor_sync(0xffffffffu, sum0, 2);
        sum1 += __shfl_xor_sync(0xffffffffu, sum1, 1);
        sum1 += __shfl_xor_sync(0xffffffffu, sum1, 2);

        l0r = l0r * c0 + sum0;
        l1r = l1r * c1 + sum1;
        m0r = mn0;
        m1r = mn1;

#pragma unroll
        for (int nt = 0; nt < 8; nt++) {
            o[nt][0] *= c0; o[nt][1] *= c0;
            o[nt][2] *= c1; o[nt][3] *= c1;
        }

        // ---- P V (P hi only -> 1 MMA per tile)
#pragma unroll
        for (int ks = 0; ks < 4; ks++) {
            uint32_t ph[4];
            ph[0] = h2_only(sc[2 * ks][0],     sc[2 * ks][1]);
            ph[1] = h2_only(sc[2 * ks][2],     sc[2 * ks][3]);
            ph[2] = h2_only(sc[2 * ks + 1][0], sc[2 * ks + 1][1]);
            ph[3] = h2_only(sc[2 * ks + 1][2], sc[2 * ks + 1][3]);

            const int kr = ks * 16 + (lane & 15);
#pragma unroll
            for (int nt = 0; nt < 8; nt++) {
                uint32_t vh[2];
                const uint32_t off = (uint32_t)(kr * 128 + ((nt ^ kr) & 7) * 16);
                ldm_x2t(vh, vb + off);
                mma_fp16(o[nt], ph, vh);
            }
        }
        __syncthreads();
    }

    // ---- epilogue: write gA hi only
    const float inv0 = 1.f / l0r;
    const float inv1 = 1.f / l1r;
    const int b = bh >> 4, h = bh & 15;
    const int t0 = q0 + row0;
#pragma unroll
    for (int nt = 0; nt < 8; nt++) {
        const int col = h * DH + nt * 8 + (lane & 3) * 2;
        *(uint32_t*)(gAh + (size_t)(b * TT + t0) * DD + col) =
            h2_only(o[nt][0] * inv0, o[nt][1] * inv0);
        *(uint32_t*)(gAh + (size_t)(b * TT + t0 + 8) * DD + col) =
            h2_only(o[nt][2] * inv1, o[nt][3] * inv1);
    }
}

// ---------------------------------------------------------------------------
// Launcher
// ---------------------------------------------------------------------------
extern "C" void kernel_launch(void* const* d_in, const int* in_sizes, int n_in,
                              void* d_out, int out_size)
{
    const float* x      = (const float*)d_in[0];
    const float* W_attn = (const float*)d_in[1];
    const float* b_attn = (const float*)d_in[2];
    const float* W_proj = (const float*)d_in[3];
    const float* b_proj = (const float*)d_in[4];
    float* out = (float*)d_out;

    cudaFuncSetAttribute(gemm2<0>, cudaFuncAttributeMaxDynamicSharedMemorySize, GSMEM);
    cudaFuncSetAttribute(gemm2<1>, cudaFuncAttributeMaxDynamicSharedMemorySize, GSMEM);
    cudaFuncSetAttribute(flash2,   cudaFuncAttributeMaxDynamicSharedMemorySize, 65536);

    prep_x<<<(MM * DD / 4 + 255) / 256, 256>>>((const float4*)x, MM * DD / 4);
    prep_w<1><<<(DD * N_QKV / 4 + 255) / 256, 256>>>((const float4*)W_attn, DD * N_QKV / 4);
    prep_w<2><<<(DD * DD / 4 + 255) / 256, 256>>>((const float4*)W_proj, DD * DD / 4);

    dim3 g1(N_QKV / BN, MM / BM);       // 24 x 32
    gemm2<0><<<g1, 512, GSMEM>>>(b_attn, nullptr);

    dim3 g2(BB * HH, TT / 128);         // 32 x 16
    flash2<<<g2, 256, 65536>>>();

    dim3 g3(DD / BN, MM / BM);          // 8 x 32
    gemm2<1><<<g3, 512, GSMEM>>>(b_proj, out);
}

// round 16
// speedup vs baseline: 1.3304x; 1.0288x over previous
#include <cuda_runtime.h>
#include <cuda_fp16.h>
#include <cstdint>

// Problem constants
#define BB 2
#define TT 2048
#define DD 1024
#define HH 16
#define DH 64
#define MM (BB*TT)          // 4096
#define N_QKV (3*DD)        // 3072

// ---------------------------------------------------------------------------
// Persistent split-fp16 scratch. X and Q keep hi+lo; everything else hi only.
// ---------------------------------------------------------------------------
__device__ __align__(16) __half Xh[MM*DD],  Xl[MM*DD];
__device__ __align__(16) __half Wah[DD*N_QKV];        // hi only (B operand)
__device__ __align__(16) __half Wph[DD*DD];           // hi only (B operand)
__device__ __align__(16) __half gQh[BB*HH*TT*DH], gQl[BB*HH*TT*DH];
__device__ __align__(16) __half gKh[BB*HH*TT*DH];     // hi only (B operand)
__device__ __align__(16) __half gVh[BB*HH*TT*DH];     // hi only (B operand)
__device__ __align__(16) __half gAh[MM*DD];           // hi only (A operand, 1-term proj)

// ---------------------------------------------------------------------------
// Helpers (baseline PTX: ldmatrix, mma.sync, cp.async — all sm_80)
// ---------------------------------------------------------------------------
__device__ __forceinline__ uint32_t smem_u32(const void* p) {
    uint32_t a;
    asm("{ .reg .u64 t; cvta.to.shared.u64 t, %1; cvt.u32.u64 %0, t; }"
        : "=r"(a) : "l"(p));
    return a;
}

__device__ __forceinline__ void ldm_x4(uint32_t* r, uint32_t addr) {
    asm volatile("ldmatrix.sync.aligned.m8n8.x4.shared.b16 {%0,%1,%2,%3}, [%4];"
                 : "=r"(r[0]), "=r"(r[1]), "=r"(r[2]), "=r"(r[3]) : "r"(addr));
}
__device__ __forceinline__ void ldm_x2(uint32_t* r, uint32_t addr) {
    asm volatile("ldmatrix.sync.aligned.m8n8.x2.shared.b16 {%0,%1}, [%2];"
                 : "=r"(r[0]), "=r"(r[1]) : "r"(addr));
}
__device__ __forceinline__ void ldm_x2t(uint32_t* r, uint32_t addr) {
    asm volatile("ldmatrix.sync.aligned.m8n8.x2.trans.shared.b16 {%0,%1}, [%2];"
                 : "=r"(r[0]), "=r"(r[1]) : "r"(addr));
}
__device__ __forceinline__ void mma_fp16(float* c, const uint32_t* a, const uint32_t* b) {
    asm volatile(
        "mma.sync.aligned.m16n8k16.row.col.f32.f16.f16.f32 "
        "{%0,%1,%2,%3}, {%4,%5,%6,%7}, {%8,%9}, {%0,%1,%2,%3};"
        : "+f"(c[0]), "+f"(c[1]), "+f"(c[2]), "+f"(c[3])
        : "r"(a[0]), "r"(a[1]), "r"(a[2]), "r"(a[3]), "r"(b[0]), "r"(b[1]));
}
__device__ __forceinline__ uint32_t pack_h2(__half a, __half b) {
    __half2 t(a, b);
    return *reinterpret_cast<uint32_t*>(&t);
}
__device__ __forceinline__ void split2h(float x, float y, uint32_t& hi, uint32_t& lo) {
    __half hx = __float2half(x);
    __half hy = __float2half(y);
    __half lx = __float2half(x - __half2float(hx));
    __half ly = __float2half(y - __half2float(hy));
    hi = pack_h2(hx, hy);
    lo = pack_h2(lx, ly);
}
__device__ __forceinline__ uint32_t h2_only(float x, float y) {
    return pack_h2(__float2half(x), __float2half(y));
}
__device__ __forceinline__ void cp16(uint32_t dst, const void* src) {
    asm volatile("cp.async.cg.shared.global [%0], [%1], 16;"
                 :: "r"(dst), "l"(src) : "memory");
}
#define CP_COMMIT() asm volatile("cp.async.commit_group;" ::: "memory")
#define CP_WAIT1()  asm volatile("cp.async.wait_group 1;" ::: "memory")
#define CP_WAIT0()  asm volatile("cp.async.wait_group 0;" ::: "memory")

// ---------------------------------------------------------------------------
// Prep kernels (X split hi/lo, weights hi only)
// ---------------------------------------------------------------------------
__global__ void prep_x(const float4* __restrict__ in, int n4)
{
    const int i = blockIdx.x * blockDim.x + threadIdx.x;
    if (i < n4) {
        float4 v = __ldg(in + i);
        uint32_t h0, l0, h1, l1;
        split2h(v.x, v.y, h0, l0);
        split2h(v.z, v.w, h1, l1);
        ((uint2*)Xh)[i] = make_uint2(h0, h1);
        ((uint2*)Xl)[i] = make_uint2(l0, l1);
    }
}
template <int WHICH>   // 1 = W_attn, 2 = W_proj
__global__ void prep_w(const float4* __restrict__ in, int n4)
{
    __half* oh = (WHICH == 1) ? Wah : Wph;
    const int i = blockIdx.x * blockDim.x + threadIdx.x;
    if (i < n4) {
        float4 v = __ldg(in + i);
        ((uint2*)oh)[i] = make_uint2(h2_only(v.x, v.y), h2_only(v.z, v.w));
    }
}

// ---------------------------------------------------------------------------
// Pipelined fp16 tensor-core GEMM. R15 geometry (512 thr / 16 warps, 32x32
// warp tiles, 3-stage cp.async, one __syncthreads per K-step) PLUS explicit
// fragment double-buffering: LDSM for chunk kk+1 issued BEFORE MMAs of chunk
// kk, breaking the per-step LDSM-storm/HMMA-storm phase serialization.
// MODE 0 (qkv): A = X hi+lo (2 MMAs/k16). MODE 1 (proj): A = gA hi (1 MMA).
// Stage layout: Ah@0 (16K) | Al@16384 (16K, MODE0 only) | Bh@32768 (16K).
// ---------------------------------------------------------------------------
#define BM 128
#define BN 128
#define GSTG 49152
#define GSMEM (3 * GSTG)

template <int MODE>
__global__ __launch_bounds__(512, 1) void gemm2(
    const float* __restrict__ bias, float* __restrict__ C)
{
    extern __shared__ char smem[];
    const uint32_t sbase = smem_u32(smem);
    const __half* Ahp = (MODE == 0) ? Xh : gAh;
    const __half* Alp = Xl;                      // only used when MODE == 0
    const __half* Bhp = (MODE == 0) ? Wah : Wph;
    const int Nn = (MODE == 0) ? N_QKV : DD;
    const int n0 = blockIdx.x * BN;
    const int m0 = blockIdx.y * BM;
    const int tid = threadIdx.x;
    const int lane = tid & 31;
    const int wid = tid >> 5;
    const int wm = wid & 3;       // rows wm*32
    const int wn = wid >> 2;      // cols wn*32

    auto issue = [&](int step) {
        const uint32_t sb = sbase + (step % 3) * GSTG;
        const int k0 = step * 64;
        {   // A tile: 128 rows x 64 fp16; 4 threads/row, 2 chunks each
            const int r = tid >> 2, c0 = (tid & 3) * 2;
            const __half* sh = Ahp + (size_t)(m0 + r) * DD + k0 + c0 * 8;
            const __half* sl = Alp + (size_t)(m0 + r) * DD + k0 + c0 * 8;
            const uint32_t db = sb + r * 128;
#pragma unroll
            for (int i = 0; i < 2; i++) {
                const int c = c0 + i;
                const uint32_t sw = (uint32_t)(((c ^ r) & 7) * 16);
                cp16(db + sw, sh + i * 8);
                if (MODE == 0) cp16(db + 16384 + sw, sl + i * 8);
            }
        }
        {   // B tile (hi only): 64 rows x 128 fp16; 8 threads/row, 2 chunks each
            const int r = tid >> 3, c0 = (tid & 7) * 2;
            const __half* sh = Bhp + (size_t)(k0 + r) * Nn + n0 + c0 * 8;
            const uint32_t db = sb + 32768 + r * 256;
#pragma unroll
            for (int i = 0; i < 2; i++) {
                const int c = c0 + i;
                const uint32_t sw = (uint32_t)((((c & 8) | ((c ^ r) & 7))) * 16);
                cp16(db + sw, sh + i * 8);
            }
        }
    };

    float acc[2][4][4];
#pragma unroll
    for (int mt = 0; mt < 2; mt++)
#pragma unroll
        for (int nt = 0; nt < 4; nt++)
#pragma unroll
            for (int e = 0; e < 4; e++) acc[mt][nt][e] = 0.f;

    // double-buffered fragments
    uint32_t ah[2][2][4], al[2][2][4], bh[2][4][2];
    const int rb_base = wm * 32 + (lane & 7) + ((lane >> 3) & 1) * 8;

    issue(0); CP_COMMIT();
    issue(1); CP_COMMIT();

    for (int step = 0; step < 16; step++) {
        if (step == 15) { CP_WAIT0(); } else { CP_WAIT1(); }
        __syncthreads();

        const uint32_t sb = sbase + (step % 3) * GSTG;

        auto ldfrag = [&](int kk, int buf) {
            const int ch = kk * 2 + (lane >> 4);
#pragma unroll
            for (int mt = 0; mt < 2; mt++) {
                const int r = rb_base + mt * 16;
                const uint32_t off = (uint32_t)(r * 128 + ((ch ^ r) & 7) * 16);
                ldm_x4(ah[buf][mt], sb + off);
                if (MODE == 0) ldm_x4(al[buf][mt], sb + 16384 + off);
            }
            const int kr = kk * 16 + (lane & 15);
#pragma unroll
            for (int nt = 0; nt < 4; nt++) {
                const int cB = wn * 4 + nt;
                const uint32_t off =
                    (uint32_t)(kr * 256 + ((cB & 8) | ((cB ^ kr) & 7)) * 16);
                ldm_x2t(bh[buf][nt], sb + 32768 + off);
            }
        };

        ldfrag(0, 0);
#pragma unroll
        for (int kk = 0; kk < 4; kk++) {
            // prefetch next chunk's fragments before this chunk's MMAs
            if (kk + 1 < 4) ldfrag(kk + 1, (kk + 1) & 1);
            const int b = kk & 1;
#pragma unroll
            for (int mt = 0; mt < 2; mt++)
#pragma unroll
                for (int nt = 0; nt < 4; nt++) {
                    mma_fp16(acc[mt][nt], ah[b][mt], bh[b][nt]);
                    if (MODE == 0) mma_fp16(acc[mt][nt], al[b][mt], bh[b][nt]);
                }
            // spread the global-load issue into the middle of the step
            if (kk == 0 && step + 2 < 16) { issue(step + 2); CP_COMMIT(); }
        }
    }

    // epilogue
#pragma unroll
    for (int mt = 0; mt < 2; mt++) {
        const int rb = m0 + wm * 32 + mt * 16 + (lane >> 2);
#pragma unroll
        for (int nt = 0; nt < 4; nt++) {
            const int col = n0 + wn * 32 + nt * 8 + (lane & 3) * 2;
            const float2 bv = *(const float2*)(bias + col);
#pragma unroll
            for (int rr = 0; rr < 2; rr++) {
                const int m = rb + rr * 8;
                float vx = acc[mt][nt][rr * 2 + 0] + bv.x;
                float vy = acc[mt][nt][rr * 2 + 1] + bv.y;
                if (MODE == 0) {
                    const int which = col >> 10;
                    const int h = (col & (DD - 1)) >> 6;
                    const int dd = col & (DH - 1);
                    const int b = m >> 11, t = m & (TT - 1);
                    const size_t idx = (((size_t)(b * HH + h) * TT) + t) * DH + dd;
                    if (which == 0) {          // Q: pre-scale + hi/lo split
                        uint32_t hi, lo;
                        split2h(vx * 0.125f, vy * 0.125f, hi, lo);
                        *(uint32_t*)(gQh + idx) = hi;
                        *(uint32_t*)(gQl + idx) = lo;
                    } else if (which == 1) {   // K: hi only
                        *(uint32_t*)(gKh + idx) = h2_only(vx, vy);
                    } else {                   // V: hi only
                        *(uint32_t*)(gVh + idx) = h2_only(vx, vy);
                    }
                } else {
                    *(float2*)(C + (size_t)m * DD + col) = make_float2(vx, vy);
                }
            }
        }
    }
}

// ---------------------------------------------------------------------------
// Tensor-core flash attention, fp16 (unchanged from R15). 128-row q-tiles,
// 256 thr / 8 warps. QK: 2-term Q split; PV: P hi only. Output gA hi only.
// smem: Qh 16K | Ql 16K | 2 stages x (Kh 8K | Vh 8K) = 64KB.
// ---------------------------------------------------------------------------
#define FSTG 16384

__global__ __launch_bounds__(256) void flash2()
{
    extern __shared__ char smem[];
    const uint32_t sbase = smem_u32(smem);
    const int bh = blockIdx.x;
    const int qt = gridDim.y - 1 - blockIdx.y;      // big tiles first
    const int q0 = qt * 128;
    const int tid = threadIdx.x;
    const int lane = tid & 31;
    const int wq = tid >> 5;                        // 0..7 -> rows wq*16
    const size_t hoff = (size_t)bh * TT * DH;

    // ---- stage Q hi/lo (128 rows)
    {
        const int r = tid >> 1, cb = (tid & 1) * 4;
        const size_t go = hoff + (size_t)(q0 + r) * DH + cb * 8;
        const uint32_t db = sbase + r * 128;
#pragma unroll
        for (int i = 0; i < 4; i++) {
            const int c = cb + i;
            const uint32_t sw = (uint32_t)(((c ^ r) & 7) * 16);
            cp16(db + sw, gQh + go + i * 8);
            cp16(db + 16384 + sw, gQl + go + i * 8);
        }
    }
    CP_COMMIT();

    const int njt = 2 * qt + 2;   // j-tiles (64 keys each) covering q0+127

    auto issueKV = [&](int jt) {
        const uint32_t db0 = sbase + 32768 + (jt & 1) * FSTG;
        const int j0 = jt * 64;
        const int r = tid >> 2, c0 = (tid & 3) * 2;
        const size_t go = hoff + (size_t)(j0 + r) * DH + c0 * 8;
        const uint32_t db = db0 + r * 128;
#pragma unroll
        for (int i = 0; i < 2; i++) {
            const int c = c0 + i;
            const uint32_t sw = (uint32_t)(((c ^ r) & 7) * 16);
            cp16(db + sw,        gKh + go + i * 8);
            cp16(db + 8192 + sw, gVh + go + i * 8);
        }
    };

    issueKV(0); CP_COMMIT();
    CP_WAIT1(); __syncthreads();

    uint32_t qh[4][4], ql[4][4];
    {
        const int r = wq * 16 + (lane & 7) + ((lane >> 3) & 1) * 8;
#pragma unroll
        for (int ks = 0; ks < 4; ks++) {
            const int ch = ks * 2 + (lane >> 4);
            const uint32_t off = (uint32_t)(r * 128 + ((ch ^ r) & 7) * 16);
            ldm_x4(qh[ks], sbase + off);
            ldm_x4(ql[ks], sbase + 16384 + off);
        }
    }

    float o[8][4];
#pragma unroll
    for (int nt = 0; nt < 8; nt++)
#pragma unroll
        for (int e = 0; e < 4; e++) o[nt][e] = 0.f;
    float m0r = -1e30f, m1r = -1e30f, l0r = 0.f, l1r = 0.f;
    const int row0 = wq * 16 + (lane >> 2);   // local q row (also +8)

    for (int jt = 0; jt < njt; jt++) {
        if (jt + 1 < njt) { issueKV(jt + 1); CP_COMMIT(); CP_WAIT1(); }
        else              { CP_WAIT0(); }
        __syncthreads();

        const uint32_t kb = sbase + 32768 + (jt & 1) * FSTG;
        const uint32_t vb = kb + 8192;

        // ---- S = Q K^T (2 MMAs per tile: Qh*K + Ql*K)
        float sc[8][4];
#pragma unroll
        for (int nt = 0; nt < 8; nt++)
#pragma unroll
            for (int e = 0; e < 4; e++) sc[nt][e] = 0.f;

#pragma unroll
        for (int ks = 0; ks < 4; ks++) {
            uint32_t bh2[8][2];
            const int ln = lane & 15;
            const int ch = ks * 2 + ((ln >> 3) & 1);
#pragma unroll
            for (int nt = 0; nt < 8; nt++) {
                const int r = nt * 8 + (ln & 7);
                const uint32_t off = (uint32_t)(r * 128 + ((ch ^ r) & 7) * 16);
                ldm_x2(bh2[nt], kb + off);
            }
#pragma unroll
            for (int nt = 0; nt < 8; nt++) {
                mma_fp16(sc[nt], qh[ks], bh2[nt]);
                mma_fp16(sc[nt], ql[ks], bh2[nt]);
            }
        }

        // ---- causal mask (last two j-tiles intersect the diagonal)
        if (jt >= 2 * qt) {
            const int j0 = jt * 64;
            const int cbase = j0 + (lane & 3) * 2;
            const int rg0 = q0 + row0;
#pragma unroll
            for (int nt = 0; nt < 8; nt++) {
                const int c0 = cbase + nt * 8;
                if (c0 > rg0)         sc[nt][0] = -1e30f;
                if (c0 + 1 > rg0)     sc[nt][1] = -1e30f;
                if (c0 > rg0 + 8)     sc[nt][2] = -1e30f;
                if (c0 + 1 > rg0 + 8) sc[nt][3] = -1e30f;
            }
        }

        // ---- online softmax
        float mx0 = -1e30f, mx1 = -1e30f;
#pragma unroll
        for (int nt = 0; nt < 8; nt++) {
            mx0 = fmaxf(mx0, fmaxf(sc[nt][0], sc[nt][1]));
            mx1 = fmaxf(mx1, fmaxf(sc[nt][2], sc[nt][3]));
        }
        mx0 = fmaxf(mx0, __shfl_xor_sync(0xffffffffu, mx0, 1));
        mx0 = fmaxf(mx0, __shfl_xor_sync(0xffffffffu, mx0, 2));
        mx1 = fmaxf(mx1, __shfl_xor_sync(0xffffffffu, mx1, 1));
        mx1 = fmaxf(mx1, __shfl_xor_sync(0xffffffffu, mx1, 2));

        const float mn0 = fmaxf(m0r, mx0);
        const float mn1 = fmaxf(m1r, mx1);
        const float c0 = __expf(m0r - mn0);
        const float c1 = __expf(m1r - mn1);

        float sum0 = 0.f, sum1 = 0.f;
#pragma unroll
        for (int nt = 0; nt < 8; nt++) {
            sc[nt][0] = __expf(sc[nt][0] - mn0);
            sc[nt][1] = __expf(sc[nt][1] - mn0);
            sc[nt][2] = __expf(sc[nt][2] - mn1);
            sc[nt][3] = __expf(sc[nt][3] - mn1);
            sum0 += sc[nt][0] + sc[nt][1];
            sum1 += sc[nt][2] + sc[nt][3];
        }
        sum0 += __shfl_xor_sync(0xffffffffu, sum0, 1);
        sum0 += __shfl_xor_sync(0xffffffffu, sum0, 2);
        sum1 += __shfl_xor_sync(0xffffffffu, sum1, 1);
        sum1 += __shfl_xor_sync(0xffffffffu, sum1, 2);

        l0r = l0r * c0 + sum0;
        l1r = l1r * c1 + sum1;
        m0r = mn0;
        m1r = mn1;

#pragma unroll
        for (int nt = 0; nt < 8; nt++) {
            o[nt][0] *= c0; o[nt][1] *= c0;
            o[nt][2] *= c1; o[nt][3] *= c1;
        }

        // ---- P V (P hi only -> 1 MMA per tile)
#pragma unroll
        for (int ks = 0; ks < 4; ks++) {
            uint32_t ph[4];
            ph[0] = h2_only(sc[2 * ks][0],     sc[2 * ks][1]);
            ph[1] = h2_only(sc[2 * ks][2],     sc[2 * ks][3]);
            ph[2] = h2_only(sc[2 * ks + 1][0], sc[2 * ks + 1][1]);
            ph[3] = h2_only(sc[2 * ks + 1][2], sc[2 * ks + 1][3]);

            const int kr = ks * 16 + (lane & 15);
#pragma unroll
            for (int nt = 0; nt < 8; nt++) {
                uint32_t vh[2];
                const uint32_t off = (uint32_t)(kr * 128 + ((nt ^ kr) & 7) * 16);
                ldm_x2t(vh, vb + off);
                mma_fp16(o[nt], ph, vh);
            }
        }
        __syncthreads();
    }

    // ---- epilogue: write gA hi only
    const float inv0 = 1.f / l0r;
    const float inv1 = 1.f / l1r;
    const int b = bh >> 4, h = bh & 15;
    const int t0 = q0 + row0;
#pragma unroll
    for (int nt = 0; nt < 8; nt++) {
        const int col = h * DH + nt * 8 + (lane & 3) * 2;
        *(uint32_t*)(gAh + (size_t)(b * TT + t0) * DD + col) =
            h2_only(o[nt][0] * inv0, o[nt][1] * inv0);
        *(uint32_t*)(gAh + (size_t)(b * TT + t0 + 8) * DD + col) =
            h2_only(o[nt][2] * inv1, o[nt][3] * inv1);
    }
}

// ---------------------------------------------------------------------------
// Launcher
// ---------------------------------------------------------------------------
extern "C" void kernel_launch(void* const* d_in, const int* in_sizes, int n_in,
                              void* d_out, int out_size)
{
    const float* x      = (const float*)d_in[0];
    const float* W_attn = (const float*)d_in[1];
    const float* b_attn = (const float*)d_in[2];
    const float* W_proj = (const float*)d_in[3];
    const float* b_proj = (const float*)d_in[4];
    float* out = (float*)d_out;

    cudaFuncSetAttribute(gemm2<0>, cudaFuncAttributeMaxDynamicSharedMemorySize, GSMEM);
    cudaFuncSetAttribute(gemm2<1>, cudaFuncAttributeMaxDynamicSharedMemorySize, GSMEM);
    cudaFuncSetAttribute(flash2,   cudaFuncAttributeMaxDynamicSharedMemorySize, 65536);

    prep_x<<<(MM * DD / 4 + 255) / 256, 256>>>((const float4*)x, MM * DD / 4);
    prep_w<1><<<(DD * N_QKV / 4 + 255) / 256, 256>>>((const float4*)W_attn, DD * N_QKV / 4);
    prep_w<2><<<(DD * DD / 4 + 255) / 256, 256>>>((const float4*)W_proj, DD * DD / 4);

    dim3 g1(N_QKV / BN, MM / BM);       // 24 x 32
    gemm2<0><<<g1, 512, GSMEM>>>(b_attn, nullptr);

    dim3 g2(BB * HH, TT / 128);         // 32 x 16
    flash2<<<g2, 256, 65536>>>();

    dim3 g3(DD / BN, MM / BM);          // 8 x 32
    gemm2<1><<<g3, 512, GSMEM>>>(b_proj, out);
}

// round 17
// speedup vs baseline: 1.3370x; 1.0049x over previous
#include <cuda_runtime.h>
#include <cuda_fp16.h>
#include <cstdint>

// Problem constants
#define BB 2
#define TT 2048
#define DD 1024
#define HH 16
#define DH 64
#define MM (BB*TT)          // 4096
#define N_QKV (3*DD)        // 3072

// ---------------------------------------------------------------------------
// Persistent split-fp16 scratch. X and Q keep hi+lo; everything else hi only.
// ---------------------------------------------------------------------------
__device__ __align__(16) __half Xh[MM*DD],  Xl[MM*DD];
__device__ __align__(16) __half Wah[DD*N_QKV];        // hi only (B operand)
__device__ __align__(16) __half Wph[DD*DD];           // hi only (B operand)
__device__ __align__(16) __half gQh[BB*HH*TT*DH], gQl[BB*HH*TT*DH];
__device__ __align__(16) __half gKh[BB*HH*TT*DH];     // hi only (B operand)
__device__ __align__(16) __half gVh[BB*HH*TT*DH];     // hi only (B operand)
__device__ __align__(16) __half gAh[MM*DD];           // hi only (A operand, 1-term proj)

// ---------------------------------------------------------------------------
// Helpers (baseline PTX: ldmatrix, mma.sync, cp.async — all sm_80)
// ---------------------------------------------------------------------------
__device__ __forceinline__ uint32_t smem_u32(const void* p) {
    uint32_t a;
    asm("{ .reg .u64 t; cvta.to.shared.u64 t, %1; cvt.u32.u64 %0, t; }"
        : "=r"(a) : "l"(p));
    return a;
}

__device__ __forceinline__ void ldm_x4(uint32_t* r, uint32_t addr) {
    asm volatile("ldmatrix.sync.aligned.m8n8.x4.shared.b16 {%0,%1,%2,%3}, [%4];"
                 : "=r"(r[0]), "=r"(r[1]), "=r"(r[2]), "=r"(r[3]) : "r"(addr));
}
__device__ __forceinline__ void ldm_x2(uint32_t* r, uint32_t addr) {
    asm volatile("ldmatrix.sync.aligned.m8n8.x2.shared.b16 {%0,%1}, [%2];"
                 : "=r"(r[0]), "=r"(r[1]) : "r"(addr));
}
__device__ __forceinline__ void ldm_x2t(uint32_t* r, uint32_t addr) {
    asm volatile("ldmatrix.sync.aligned.m8n8.x2.trans.shared.b16 {%0,%1}, [%2];"
                 : "=r"(r[0]), "=r"(r[1]) : "r"(addr));
}
__device__ __forceinline__ void mma_fp16(float* c, const uint32_t* a, const uint32_t* b) {
    asm volatile(
        "mma.sync.aligned.m16n8k16.row.col.f32.f16.f16.f32 "
        "{%0,%1,%2,%3}, {%4,%5,%6,%7}, {%8,%9}, {%0,%1,%2,%3};"
        : "+f"(c[0]), "+f"(c[1]), "+f"(c[2]), "+f"(c[3])
        : "r"(a[0]), "r"(a[1]), "r"(a[2]), "r"(a[3]), "r"(b[0]), "r"(b[1]));
}
__device__ __forceinline__ uint32_t pack_h2(__half a, __half b) {
    __half2 t(a, b);
    return *reinterpret_cast<uint32_t*>(&t);
}
__device__ __forceinline__ void split2h(float x, float y, uint32_t& hi, uint32_t& lo) {
    __half hx = __float2half(x);
    __half hy = __float2half(y);
    __half lx = __float2half(x - __half2float(hx));
    __half ly = __float2half(y - __half2float(hy));
    hi = pack_h2(hx, hy);
    lo = pack_h2(lx, ly);
}
// single-instruction pack: {lo=x, hi=y}
__device__ __forceinline__ uint32_t h2_only(float x, float y) {
    uint32_t r;
    asm("cvt.rn.f16x2.f32 %0, %1, %2;" : "=r"(r) : "f"(y), "f"(x));
    return r;
}
__device__ __forceinline__ void cp16(uint32_t dst, const void* src) {
    asm volatile("cp.async.cg.shared.global [%0], [%1], 16;"
                 :: "r"(dst), "l"(src) : "memory");
}
#define CP_COMMIT() asm volatile("cp.async.commit_group;" ::: "memory")
#define CP_WAIT1()  asm volatile("cp.async.wait_group 1;" ::: "memory")
#define CP_WAIT0()  asm volatile("cp.async.wait_group 0;" ::: "memory")

// ---------------------------------------------------------------------------
// Prep kernels (X split hi/lo, weights hi only)
// ---------------------------------------------------------------------------
__global__ void prep_x(const float4* __restrict__ in, int n4)
{
    const int i = blockIdx.x * blockDim.x + threadIdx.x;
    if (i < n4) {
        float4 v = __ldg(in + i);
        uint32_t h0, l0, h1, l1;
        split2h(v.x, v.y, h0, l0);
        split2h(v.z, v.w, h1, l1);
        ((uint2*)Xh)[i] = make_uint2(h0, h1);
        ((uint2*)Xl)[i] = make_uint2(l0, l1);
    }
}
template <int WHICH>   // 1 = W_attn, 2 = W_proj
__global__ void prep_w(const float4* __restrict__ in, int n4)
{
    __half* oh = (WHICH == 1) ? Wah : Wph;
    const int i = blockIdx.x * blockDim.x + threadIdx.x;
    if (i < n4) {
        float4 v = __ldg(in + i);
        ((uint2*)oh)[i] = make_uint2(h2_only(v.x, v.y), h2_only(v.z, v.w));
    }
}

// ---------------------------------------------------------------------------
// Pipelined fp16 tensor-core GEMM (unchanged from R16: 512 thr / 16 warps,
// 32x32 warp tiles, 3-stage cp.async, fragment double-buffering).
// MODE 0 (qkv): A = X hi+lo (2 MMAs/k16). MODE 1 (proj): A = gA hi (1 MMA).
// ---------------------------------------------------------------------------
#define BM 128
#define BN 128
#define GSTG 49152
#define GSMEM (3 * GSTG)

template <int MODE>
__global__ __launch_bounds__(512, 1) void gemm2(
    const float* __restrict__ bias, float* __restrict__ C)
{
    extern __shared__ char smem[];
    const uint32_t sbase = smem_u32(smem);
    const __half* Ahp = (MODE == 0) ? Xh : gAh;
    const __half* Alp = Xl;                      // only used when MODE == 0
    const __half* Bhp = (MODE == 0) ? Wah : Wph;
    const int Nn = (MODE == 0) ? N_QKV : DD;
    const int n0 = blockIdx.x * BN;
    const int m0 = blockIdx.y * BM;
    const int tid = threadIdx.x;
    const int lane = tid & 31;
    const int wid = tid >> 5;
    const int wm = wid & 3;       // rows wm*32
    const int wn = wid >> 2;      // cols wn*32

    auto issue = [&](int step) {
        const uint32_t sb = sbase + (step % 3) * GSTG;
        const int k0 = step * 64;
        {
            const int r = tid >> 2, c0 = (tid & 3) * 2;
            const __half* sh = Ahp + (size_t)(m0 + r) * DD + k0 + c0 * 8;
            const __half* sl = Alp + (size_t)(m0 + r) * DD + k0 + c0 * 8;
            const uint32_t db = sb + r * 128;
#pragma unroll
            for (int i = 0; i < 2; i++) {
                const int c = c0 + i;
                const uint32_t sw = (uint32_t)(((c ^ r) & 7) * 16);
                cp16(db + sw, sh + i * 8);
                if (MODE == 0) cp16(db + 16384 + sw, sl + i * 8);
            }
        }
        {
            const int r = tid >> 3, c0 = (tid & 7) * 2;
            const __half* sh = Bhp + (size_t)(k0 + r) * Nn + n0 + c0 * 8;
            const uint32_t db = sb + 32768 + r * 256;
#pragma unroll
            for (int i = 0; i < 2; i++) {
                const int c = c0 + i;
                const uint32_t sw = (uint32_t)((((c & 8) | ((c ^ r) & 7))) * 16);
                cp16(db + sw, sh + i * 8);
            }
        }
    };

    float acc[2][4][4];
#pragma unroll
    for (int mt = 0; mt < 2; mt++)
#pragma unroll
        for (int nt = 0; nt < 4; nt++)
#pragma unroll
            for (int e = 0; e < 4; e++) acc[mt][nt][e] = 0.f;

    uint32_t ah[2][2][4], al[2][2][4], bh[2][4][2];
    const int rb_base = wm * 32 + (lane & 7) + ((lane >> 3) & 1) * 8;

    issue(0); CP_COMMIT();
    issue(1); CP_COMMIT();

    for (int step = 0; step < 16; step++) {
        if (step == 15) { CP_WAIT0(); } else { CP_WAIT1(); }
        __syncthreads();

        const uint32_t sb = sbase + (step % 3) * GSTG;

        auto ldfrag = [&](int kk, int buf) {
            const int ch = kk * 2 + (lane >> 4);
#pragma unroll
            for (int mt = 0; mt < 2; mt++) {
                const int r = rb_base + mt * 16;
                const uint32_t off = (uint32_t)(r * 128 + ((ch ^ r) & 7) * 16);
                ldm_x4(ah[buf][mt], sb + off);
                if (MODE == 0) ldm_x4(al[buf][mt], sb + 16384 + off);
            }
            const int kr = kk * 16 + (lane & 15);
#pragma unroll
            for (int nt = 0; nt < 4; nt++) {
                const int cB = wn * 4 + nt;
                const uint32_t off =
                    (uint32_t)(kr * 256 + ((cB & 8) | ((cB ^ kr) & 7)) * 16);
                ldm_x2t(bh[buf][nt], sb + 32768 + off);
            }
        };

        ldfrag(0, 0);
#pragma unroll
        for (int kk = 0; kk < 4; kk++) {
            if (kk + 1 < 4) ldfrag(kk + 1, (kk + 1) & 1);
            const int b = kk & 1;
#pragma unroll
            for (int mt = 0; mt < 2; mt++)
#pragma unroll
                for (int nt = 0; nt < 4; nt++) {
                    mma_fp16(acc[mt][nt], ah[b][mt], bh[b][nt]);
                    if (MODE == 0) mma_fp16(acc[mt][nt], al[b][mt], bh[b][nt]);
                }
            if (kk == 0 && step + 2 < 16) { issue(step + 2); CP_COMMIT(); }
        }
    }

    // epilogue
#pragma unroll
    for (int mt = 0; mt < 2; mt++) {
        const int rb = m0 + wm * 32 + mt * 16 + (lane >> 2);
#pragma unroll
        for (int nt = 0; nt < 4; nt++) {
            const int col = n0 + wn * 32 + nt * 8 + (lane & 3) * 2;
            const float2 bv = *(const float2*)(bias + col);
#pragma unroll
            for (int rr = 0; rr < 2; rr++) {
                const int m = rb + rr * 8;
                float vx = acc[mt][nt][rr * 2 + 0] + bv.x;
                float vy = acc[mt][nt][rr * 2 + 1] + bv.y;
                if (MODE == 0) {
                    const int which = col >> 10;
                    const int h = (col & (DD - 1)) >> 6;
                    const int dd = col & (DH - 1);
                    const int b = m >> 11, t = m & (TT - 1);
                    const size_t idx = (((size_t)(b * HH + h) * TT) + t) * DH + dd;
                    if (which == 0) {
                        uint32_t hi, lo;
                        split2h(vx * 0.125f, vy * 0.125f, hi, lo);
                        *(uint32_t*)(gQh + idx) = hi;
                        *(uint32_t*)(gQl + idx) = lo;
                    } else if (which == 1) {
                        *(uint32_t*)(gKh + idx) = h2_only(vx, vy);
                    } else {
                        *(uint32_t*)(gVh + idx) = h2_only(vx, vy);
                    }
                } else {
                    *(float2*)(C + (size_t)m * DD + col) = make_float2(vx, vy);
                }
            }
        }
    }
}

// ---------------------------------------------------------------------------
// Tensor-core flash attention, fp16. 128-row q-tiles, 256 thr / 8 warps.
// SMEM CUT TO 32KB: Q is staged through the two KV stage buffers (16KB each),
// fragments extracted to registers, then the same 32KB recycles as the KV
// double-buffer -> 2 CTAs/SM (launch_bounds(256,2), regs <= 128).
// QK: 2-term Q split; PV: P hi only. Output gA hi only.
// ---------------------------------------------------------------------------
#define FSTG 16384

__global__ __launch_bounds__(256, 2) void flash2()
{
    extern __shared__ char smem[];
    const uint32_t sbase = smem_u32(smem);
    const int bh = blockIdx.x;
    const int qt = gridDim.y - 1 - blockIdx.y;      // big tiles first
    const int q0 = qt * 128;
    const int tid = threadIdx.x;
    const int lane = tid & 31;
    const int wq = tid >> 5;                        // 0..7 -> rows wq*16
    const size_t hoff = (size_t)bh * TT * DH;

    // ---- stage Q hi into buffer 0, Q lo into buffer 1 (reused for KV later)
    {
        const int r = tid >> 1, cb = (tid & 1) * 4;
        const size_t go = hoff + (size_t)(q0 + r) * DH + cb * 8;
        const uint32_t db = sbase + r * 128;
#pragma unroll
        for (int i = 0; i < 4; i++) {
            const int c = cb + i;
            const uint32_t sw = (uint32_t)(((c ^ r) & 7) * 16);
            cp16(db + sw, gQh + go + i * 8);
            cp16(db + FSTG + sw, gQl + go + i * 8);
        }
    }
    CP_COMMIT();
    CP_WAIT0();
    __syncthreads();

    uint32_t qh[4][4], ql[4][4];
    {
        const int r = wq * 16 + (lane & 7) + ((lane >> 3) & 1) * 8;
#pragma unroll
        for (int ks = 0; ks < 4; ks++) {
            const int ch = ks * 2 + (lane >> 4);
            const uint32_t off = (uint32_t)(r * 128 + ((ch ^ r) & 7) * 16);
            ldm_x4(qh[ks], sbase + off);
            ldm_x4(ql[ks], sbase + FSTG + off);
        }
    }
    __syncthreads();   // all warps done reading Q staging; buffers now free

    const int njt = 2 * qt + 2;   // j-tiles (64 keys each) covering q0+127

    auto issueKV = [&](int jt) {
        const uint32_t db0 = sbase + (jt & 1) * FSTG;
        const int j0 = jt * 64;
        const int r = tid >> 2, c0 = (tid & 3) * 2;
        const size_t go = hoff + (size_t)(j0 + r) * DH + c0 * 8;
        const uint32_t db = db0 + r * 128;
#pragma unroll
        for (int i = 0; i < 2; i++) {
            const int c = c0 + i;
            const uint32_t sw = (uint32_t)(((c ^ r) & 7) * 16);
            cp16(db + sw,        gKh + go + i * 8);
            cp16(db + 8192 + sw, gVh + go + i * 8);
        }
    };

    issueKV(0); CP_COMMIT();

    float o[8][4];
#pragma unroll
    for (int nt = 0; nt < 8; nt++)
#pragma unroll
        for (int e = 0; e < 4; e++) o[nt][e] = 0.f;
    float m0r = -1e30f, m1r = -1e30f, l0r = 0.f, l1r = 0.f;
    const int row0 = wq * 16 + (lane >> 2);   // local q row (also +8)

    for (int jt = 0; jt < njt; jt++) {
        if (jt + 1 < njt) { issueKV(jt + 1); CP_COMMIT(); CP_WAIT1(); }
        else              { CP_WAIT0(); }
        __syncthreads();

        const uint32_t kb = sbase + (jt & 1) * FSTG;
        const uint32_t vb = kb + 8192;

        // ---- S = Q K^T (2 MMAs per tile: Qh*K + Ql*K)
        float sc[8][4];
#pragma unroll
        for (int nt = 0; nt < 8; nt++)
#pragma unroll
            for (int e = 0; e < 4; e++) sc[nt][e] = 0.f;

#pragma unroll
        for (int ks = 0; ks < 4; ks++) {
            uint32_t bh2[8][2];
            const int ln = lane & 15;
            const int ch = ks * 2 + ((ln >> 3) & 1);
#pragma unroll
            for (int nt = 0; nt < 8; nt++) {
                const int r = nt * 8 + (ln & 7);
                const uint32_t off = (uint32_t)(r * 128 + ((ch ^ r) & 7) * 16);
                ldm_x2(bh2[nt], kb + off);
            }
#pragma unroll
            for (int nt = 0; nt < 8; nt++) {
                mma_fp16(sc[nt], qh[ks], bh2[nt]);
                mma_fp16(sc[nt], ql[ks], bh2[nt]);
            }
        }

        // ---- causal mask (last two j-tiles intersect the diagonal)
        if (jt >= 2 * qt) {
            const int j0 = jt * 64;
            const int cbase = j0 + (lane & 3) * 2;
            const int rg0 = q0 + row0;
#pragma unroll
            for (int nt = 0; nt < 8; nt++) {
                const int c0 = cbase + nt * 8;
                if (c0 > rg0)         sc[nt][0] = -1e30f;
                if (c0 + 1 > rg0)     sc[nt][1] = -1e30f;
                if (c0 > rg0 + 8)     sc[nt][2] = -1e30f;
                if (c0 + 1 > rg0 + 8) sc[nt][3] = -1e30f;
            }
        }

        // ---- online softmax
        float mx0 = -1e30f, mx1 = -1e30f;
#pragma unroll
        for (int nt = 0; nt < 8; nt++) {
            mx0 = fmaxf(mx0, fmaxf(sc[nt][0], sc[nt][1]));
            mx1 = fmaxf(mx1, fmaxf(sc[nt][2], sc[nt][3]));
        }
        mx0 = fmaxf(mx0, __shfl_xor_sync(0xffffffffu, mx0, 1));
        mx0 = fmaxf(mx0, __shfl_xor_sync(0xffffffffu, mx0, 2));
        mx1 = fmaxf(mx1, __shfl_xor_sync(0xffffffffu, mx1, 1));
        mx1 = fmaxf(mx1, __shfl_xor_sync(0xffffffffu, mx1, 2));

        const float mn0 = fmaxf(m0r, mx0);
        const float mn1 = fmaxf(m1r, mx1);
        const float c0 = __expf(m0r - mn0);
        const float c1 = __expf(m1r - mn1);

        float sum0 = 0.f, sum1 = 0.f;
#pragma unroll
        for (int nt = 0; nt < 8; nt++) {
            sc[nt][0] = __expf(sc[nt][0] - mn0);
            sc[nt][1] = __expf(sc[nt][1] - mn0);
            sc[nt][2] = __expf(sc[nt][2] - mn1);
            sc[nt][3] = __expf(sc[nt][3] - mn1);
            sum0 += sc[nt][0] + sc[nt][1];
            sum1 += sc[nt][2] + sc[nt][3];
        }
        sum0 += __shfl_xor_sync(0xffffffffu, sum0, 1);
        sum0 += __shfl_xor_sync(0xffffffffu, sum0, 2);
        sum1 += __shfl_xor_sync(0xffffffffu, sum1, 1);
        sum1 += __shfl_xor_sync(0xffffffffu, sum1, 2);

        l0r = l0r * c0 + sum0;
        l1r = l1r * c1 + sum1;
        m0r = mn0;
        m1r = mn1;

#pragma unroll
        for (int nt = 0; nt < 8; nt++) {
            o[nt][0] *= c0; o[nt][1] *= c0;
            o[nt][2] *= c1; o[nt][3] *= c1;
        }

        // ---- P V (P hi only -> 1 MMA per tile)
#pragma unroll
        for (int ks = 0; ks < 4; ks++) {
            uint32_t ph[4];
            ph[0] = h2_only(sc[2 * ks][0],     sc[2 * ks][1]);
            ph[1] = h2_only(sc[2 * ks][2],     sc[2 * ks][3]);
            ph[2] = h2_only(sc[2 * ks + 1][0], sc[2 * ks + 1][1]);
            ph[3] = h2_only(sc[2 * ks + 1][2], sc[2 * ks + 1][3]);

            const int kr = ks * 16 + (lane & 15);
#pragma unroll
            for (int nt = 0; nt < 8; nt++) {
                uint32_t vh[2];
                const uint32_t off = (uint32_t)(kr * 128 + ((nt ^ kr) & 7) * 16);
                ldm_x2t(vh, vb + off);
                mma_fp16(o[nt], ph, vh);
            }
        }
        __syncthreads();
    }

    // ---- epilogue: write gA hi only
    const float inv0 = 1.f / l0r;
    const float inv1 = 1.f / l1r;
    const int b = bh >> 4, h = bh & 15;
    const int t0 = q0 + row0;
#pragma unroll
    for (int nt = 0; nt < 8; nt++) {
        const int col = h * DH + nt * 8 + (lane & 3) * 2;
        *(uint32_t*)(gAh + (size_t)(b * TT + t0) * DD + col) =
            h2_only(o[nt][0] * inv0, o[nt][1] * inv0);
        *(uint32_t*)(gAh + (size_t)(b * TT + t0 + 8) * DD + col) =
            h2_only(o[nt][2] * inv1, o[nt][3] * inv1);
    }
}

// ---------------------------------------------------------------------------
// Launcher
// ---------------------------------------------------------------------------
extern "C" void kernel_launch(void* const* d_in, const int* in_sizes, int n_in,
                              void* d_out, int out_size)
{
    const float* x      = (const float*)d_in[0];
    const float* W_attn = (const float*)d_in[1];
    const float* b_attn = (const float*)d_in[2];
    const float* W_proj = (const float*)d_in[3];
    const float* b_proj = (const float*)d_in[4];
    float* out = (float*)d_out;

    cudaFuncSetAttribute(gemm2<0>, cudaFuncAttributeMaxDynamicSharedMemorySize, GSMEM);
    cudaFuncSetAttribute(gemm2<1>, cudaFuncAttributeMaxDynamicSharedMemorySize, GSMEM);
    cudaFuncSetAttribute(flash2,   cudaFuncAttributeMaxDynamicSharedMemorySize, 2 * FSTG);

    prep_x<<<(MM * DD / 4 + 255) / 256, 256>>>((const float4*)x, MM * DD / 4);
    prep_w<1><<<(DD * N_QKV / 4 + 255) / 256, 256>>>((const float4*)W_attn, DD * N_QKV / 4);
    prep_w<2><<<(DD * DD / 4 + 255) / 256, 256>>>((const float4*)W_proj, DD * DD / 4);

    dim3 g1(N_QKV / BN, MM / BM);       // 24 x 32
    gemm2<0><<<g1, 512, GSMEM>>>(b_attn, nullptr);

    dim3 g2(BB * HH, TT / 128);         // 32 x 16
    flash2<<<g2, 256, 2 * FSTG>>>();

    dim3 g3(DD / BN, MM / BM);          // 8 x 32
    gemm2<1><<<g3, 512, GSMEM>>>(b_proj, out);
}